// round 11
// baseline (speedup 1.0000x reference)
#include <cuda_runtime.h>
#include <cuda_fp16.h>
#include <math.h>
#include <stdint.h>

// ---------------- problem constants ----------------
#define BATCH    512
#define SEQT     25
#define CH       512
#define NWIN     5
#define POOLW    5
#define BS       2560          // BATCH * NWIN
#define NROWS    5120          // 2 * BS
#define NT       40            // 128-row tiles per dim
#define NBLK     820           // NT*(NT+1)/2 upper-triangular tiles
#define TM       128
#define TEMP_INV 10.0f
#define SHIFT    10.0f
#define NCTA     296           // 148 SMs x 2 resident CTAs (guaranteed co-resident)

// ---------------- device scratch ----------------
__device__ __align__(16) __half g_znh[NROWS * CH];  // normalized rows, fp16
__device__ float g_rowS[NROWS];      // sum_j exp(logit-SHIFT), j != i
__device__ float g_rowPos[NROWS];    // positive logit per row
__device__ unsigned int g_ready;     // pool-phase grid sync (reset by finalizer)
__device__ unsigned int g_done;      // finalize ticket      (reset by finalizer)

static __device__ __forceinline__ uint32_t smem_u32(const void* p) {
    uint32_t r;
    asm("{ .reg .u64 t; cvta.to.shared.u64 t, %1; cvt.u32.u64 %0, t; }" : "=r"(r) : "l"(p));
    return r;
}

#define LDSM_X4(R, addr) \
    asm volatile("ldmatrix.sync.aligned.m8n8.x4.shared.b16 {%0,%1,%2,%3}, [%4];" \
                 : "=r"((R)[0]), "=r"((R)[1]), "=r"((R)[2]), "=r"((R)[3]) : "r"(addr))

// fp16 in, fp16 accumulate
#define MMA16816H(C, A, B0, B1) \
    asm volatile("mma.sync.aligned.m16n8k16.row.col.f16.f16.f16.f16 " \
                 "{%0,%1}, {%2,%3,%4,%5}, {%6,%7}, {%0,%1};" \
                 : "+r"((C)[0]), "+r"((C)[1]) \
                 : "r"((A)[0]), "r"((A)[1]), "r"((A)[2]), "r"((A)[3]), \
                   "r"(B0), "r"(B1))

// ---------------------------------------------------------------------------
// ONE persistent kernel: pool+normalize -> grid sync -> HMMA tiles -> finalize
// 296 CTAs x 256 threads, 38KB smem, launch_bounds(256,2) -> all co-resident.
// ---------------------------------------------------------------------------
__global__ __launch_bounds__(256, 2) void simclr_fused_kernel(
        const float* __restrict__ zi, const float* __restrict__ zj,
        float* __restrict__ out) {
    __shared__ __align__(16) __half As[TM * 72];
    __shared__ __align__(16) __half Bsm[TM * 72];
    __shared__ float rowsm[TM];
    __shared__ float colsm[TM];
    __shared__ int lastflag;

    int tid = threadIdx.x;
    int bidx = blockIdx.x;
    int wid = tid >> 5, lid = tid & 31;

    // ======================= PHASE 1: pool + normalize =======================
    {
        int zidx = bidx * 256 + tid;
        if (zidx < NROWS) g_rowS[zidx] = 0.0f;

        int half = tid >> 7;            // 0/1
        int t    = tid & 127;
        for (int r = bidx * 2 + half; r < NROWS; r += NCTA * 2) {
            const float* src = (r < BS) ? zi : zj;
            int rr = (r < BS) ? r : r - BS;
            int b  = rr / NWIN;
            int w  = rr % NWIN;
            const float* base = src + ((size_t)(b * SEQT + w * POOLW)) * CH;

            int c0 = t * 4;
            float4 acc = make_float4(0.f, 0.f, 0.f, 0.f);
#pragma unroll
            for (int tt = 0; tt < POOLW; tt++) {
                float4 v = *(const float4*)(base + (size_t)tt * CH + c0);
                acc.x += v.x; acc.y += v.y; acc.z += v.z; acc.w += v.w;
            }
            acc.x *= 0.2f; acc.y *= 0.2f; acc.z *= 0.2f; acc.w *= 0.2f;

            float ss = acc.x * acc.x + acc.y * acc.y + acc.z * acc.z + acc.w * acc.w;
#pragma unroll
            for (int o = 16; o > 0; o >>= 1) ss += __shfl_xor_sync(0xffffffffu, ss, o);

            // reuse rowsm as cross-warp scratch (8 slots)
            if ((tid & 31) == 0) rowsm[tid >> 5] = ss;
            __syncthreads();
            float tot = rowsm[half * 4] + rowsm[half * 4 + 1]
                      + rowsm[half * 4 + 2] + rowsm[half * 4 + 3];
            __syncthreads();

            float inv = 1.0f / fmaxf(sqrtf(tot), 1e-8f);
            __half2 p0 = __floats2half2_rn(acc.x * inv, acc.y * inv);
            __half2 p1 = __floats2half2_rn(acc.z * inv, acc.w * inv);
            __half* dst = g_znh + (size_t)r * CH + c0;
            *(__half2*)(dst)     = p0;
            *(__half2*)(dst + 2) = p1;
        }
    }

    // ======================= grid-wide sync (all CTAs resident) ==============
    __threadfence();                 // release pooled rows + zeroed g_rowS
    __syncthreads();
    if (tid == 0) {
        atomicAdd(&g_ready, 1u);
        while (atomicAdd(&g_ready, 0u) < (unsigned)NCTA) __nanosleep(64);
    }
    __syncthreads();
    __threadfence();                 // acquire

    int g = lid >> 2, t4 = lid & 3;
    int wr = wid & 3, wc = wid >> 2;
    uint32_t aBase = smem_u32(As), bBase = smem_u32(Bsm);

    // per-thread load slots
    int lrow[4], lch[4];
#pragma unroll
    for (int it = 0; it < 4; it++) {
        int idx = tid + it * 256;
        lrow[it] = idx >> 3;
        lch[it]  = idx & 7;
    }

    // ======================= PHASE 2: Gram tiles =============================
    for (int tile = bidx; tile < NBLK; tile += NCTA) {
        // decode tile -> (rt, ct), ct >= rt
        int rt = (int)(0.5f * (81.0f - sqrtf(81.0f * 81.0f - 8.0f * (float)tile)));
        while ((rt + 1) * NT - ((rt + 1) * rt) / 2 <= tile) rt++;
        while (rt * NT - (rt * (rt - 1)) / 2 > tile) rt--;
        int ct = rt + tile - (rt * NT - (rt * (rt - 1)) / 2);

        const bool diag = (ct == rt);
        const bool haspos = (ct == rt + 20);

        __syncthreads();             // protect rowsm/colsm reuse across tiles
        if (tid < TM) { rowsm[tid] = 0.f; colsm[tid] = 0.f; }

        uint32_t acc[2][8][2];
#pragma unroll
        for (int mi = 0; mi < 2; mi++)
#pragma unroll
            for (int na = 0; na < 8; na++) { acc[mi][na][0] = 0u; acc[mi][na][1] = 0u; }

        const __half* Ag = g_znh + (size_t)rt * TM * CH;
        const __half* Bg = g_znh + (size_t)ct * TM * CH;

        uint4 pa[4], pb[4];
#pragma unroll
        for (int it = 0; it < 4; it++) {
            pa[it] = *(const uint4*)(Ag + (size_t)lrow[it] * CH + lch[it] * 8);
            pb[it] = *(const uint4*)(Bg + (size_t)lrow[it] * CH + lch[it] * 8);
        }
#pragma unroll
        for (int it = 0; it < 4; it++) {
            *(uint4*)((char*)As  + lrow[it] * 144 + lch[it] * 16) = pa[it];
            *(uint4*)((char*)Bsm + lrow[it] * 144 + lch[it] * 16) = pb[it];
        }

        for (int c = 0; c < 8; c++) {
            __syncthreads();                   // smem chunk c ready
            if (c < 7) {
                int k0 = (c + 1) * 64;
#pragma unroll
                for (int it = 0; it < 4; it++) {
                    pa[it] = *(const uint4*)(Ag + (size_t)lrow[it] * CH + k0 + lch[it] * 8);
                    pb[it] = *(const uint4*)(Bg + (size_t)lrow[it] * CH + k0 + lch[it] * 8);
                }
            }

#pragma unroll
            for (int ks = 0; ks < 4; ks++) {
                int kk = ks * 16;
                uint32_t a[2][4];
#pragma unroll
                for (int mi = 0; mi < 2; mi++) {
                    int r = wr * 32 + mi * 16 + (lid & 15);
                    LDSM_X4(a[mi], aBase + r * 144 + (kk + (lid >> 4) * 8) * 2);
                }
                uint32_t bfr[4][4];
#pragma unroll
                for (int nb = 0; nb < 4; nb++) {
                    int r = wc * 64 + nb * 16 + (lid & 15);
                    LDSM_X4(bfr[nb], bBase + r * 144 + (kk + (lid >> 4) * 8) * 2);
                }
#pragma unroll
                for (int mi = 0; mi < 2; mi++)
#pragma unroll
                    for (int na = 0; na < 8; na++)
                        MMA16816H(acc[mi][na], a[mi],
                                  bfr[na >> 1][na & 1], bfr[na >> 1][2 + (na & 1)]);
            }

            __syncthreads();                   // done reading chunk c
            if (c < 7) {
#pragma unroll
                for (int it = 0; it < 4; it++) {
                    *(uint4*)((char*)As  + lrow[it] * 144 + lch[it] * 16) = pa[it];
                    *(uint4*)((char*)Bsm + lrow[it] * 144 + lch[it] * 16) = pb[it];
                }
            }
        }

        // ---- fused epilogue ----
        int gr0 = rt * TM, gc0 = ct * TM;
        float colacc[16];
#pragma unroll
        for (int q = 0; q < 16; q++) colacc[q] = 0.f;
        float rowpart[2][2] = {{0.f, 0.f}, {0.f, 0.f}};

#pragma unroll
        for (int mi = 0; mi < 2; mi++) {
#pragma unroll
            for (int na = 0; na < 8; na++) {
#pragma unroll
                for (int h = 0; h < 2; h++) {
                    float2 pr = __half22float2(*(const __half2*)&acc[mi][na][h]);
#pragma unroll
                    for (int e = 0; e < 2; e++) {
                        int rl = wr * 32 + mi * 16 + g + h * 8;
                        int cl = wc * 64 + na * 8 + t4 * 2 + e;
                        float sim = (e == 0) ? pr.x : pr.y;
                        float ev = __expf(sim * TEMP_INV - SHIFT);
                        if (diag && rl == cl) ev = 0.f;
                        if (haspos && rl == cl) {
                            float lg = sim * TEMP_INV;
                            g_rowPos[gr0 + rl] = lg;
                            g_rowPos[gr0 + rl + BS] = lg;
                        }
                        rowpart[mi][h] += ev;
                        colacc[na * 2 + e] += ev;
                    }
                }
            }
        }

#pragma unroll
        for (int mi = 0; mi < 2; mi++)
#pragma unroll
            for (int h = 0; h < 2; h++) {
                float v = rowpart[mi][h];
                v += __shfl_xor_sync(0xffffffffu, v, 1);
                v += __shfl_xor_sync(0xffffffffu, v, 2);
                if (t4 == 0) atomicAdd(&rowsm[wr * 32 + mi * 16 + g + h * 8], v);
            }

#pragma unroll
        for (int q = 0; q < 16; q++) {
            float v = colacc[q];
            v += __shfl_xor_sync(0xffffffffu, v, 4);
            v += __shfl_xor_sync(0xffffffffu, v, 8);
            v += __shfl_xor_sync(0xffffffffu, v, 16);
            if (g == 0) atomicAdd(&colsm[wc * 64 + (q >> 1) * 8 + t4 * 2 + (q & 1)], v);
        }
        __syncthreads();

        if (tid < TM) {
            atomicAdd(&g_rowS[gr0 + tid], rowsm[tid]);
            if (!diag) atomicAdd(&g_rowS[gc0 + tid], colsm[tid]);
        }
    }

    // ======================= PHASE 3: last-CTA finalize ======================
    __threadfence();
    __syncthreads();
    if (tid == 0) {
        unsigned int old = atomicAdd(&g_done, 1u);
        lastflag = (old == NCTA - 1) ? 1 : 0;
    }
    __syncthreads();
    if (lastflag) {
        __threadfence();
        float part = 0.f;
#pragma unroll
        for (int it = 0; it < NROWS / 256; it++) {
            int i = it * 256 + tid;
            part += SHIFT + __logf(g_rowS[i]) - g_rowPos[i];
        }
#pragma unroll
        for (int o = 16; o > 0; o >>= 1) part += __shfl_xor_sync(0xffffffffu, part, o);
        if (lid == 0) colsm[wid] = part;
        __syncthreads();
        if (tid == 0) {
            float tot = 0.f;
#pragma unroll
            for (int w = 0; w < 8; w++) tot += colsm[w];
            out[0] = tot / (float)NROWS;
            // reset tickets for the next graph replay (single writer, ordered
            // after every other CTA has passed both counters)
            g_ready = 0u;
            g_done  = 0u;
            __threadfence();
        }
    }
}

// ---------------------------------------------------------------------------
extern "C" void kernel_launch(void* const* d_in, const int* in_sizes, int n_in,
                              void* d_out, int out_size) {
    const float* zi = (const float*)d_in[0];
    const float* zj = (const float*)d_in[1];
    float* out = (float*)d_out;

    simclr_fused_kernel<<<NCTA, 256>>>(zi, zj, out);
}